// round 13
// baseline (speedup 1.0000x reference)
#include <cuda_runtime.h>

#define IN_FEATURES 212445
#define N1 65536
#define N2 16384
#define NBINS 128
#define NCLS 20
#define BATCH 32

#define ACC_THREADS 64
#define ACC_CHUNKS 25
#define NGROUPS ((IN_FEATURES + 3) / 4)   // 53112

#define HISTB 16
#define FOLDB 20
#define KBID  (HISTB + FOLDB)             // 36
#define ACC0  (KBID + 1)                  // 37
#define ACCB  (ACC_CHUNKS * BATCH)        // 800
#define TOTALB (ACC0 + ACCB)              // 837  (<= 888 co-resident slots)

// ---------------- device scratch (no allocation; zero-initialized at load) ----
__device__ unsigned int g_m8[NGROUPS];            // composed map, 4 bins/uint
__device__ __align__(16) float g_pcc1[NBINS * HISTB];   // cc1 partials [m][h]
__device__ __align__(16) float g_pcnt2[NBINS * HISTB];  // cnt2 partials [m][h]
__device__ float g_G[NCLS * NBINS];               // single-writer (fold)
__device__ float g_GB[NCLS * NBINS];
__device__ float g_GC[NCLS * NBINS];
__device__ float g_GD[NCLS];
// monotonic tickets — never reset; round r waits for (r+1)*count
__device__ unsigned int c_compose, c_fold, c_aux, c_k, c_out;

__device__ __forceinline__ void spin_ge(unsigned int* p, unsigned int tgt) {
    while (((volatile unsigned int*)p)[0] < tgt) __nanosleep(64);
}

__global__ void __launch_bounds__(ACC_THREADS) mega_kernel(
        const float* __restrict__ x,
        const int* __restrict__ p0, const int* __restrict__ p1, const int* __restrict__ p2,
        const float* __restrict__ W0, const float* __restrict__ b0,
        const float* __restrict__ W1, const float* __restrict__ b1,
        const float* __restrict__ W2, const float* __restrict__ b2,
        const float* __restrict__ fcw, const float* __restrict__ fcb,
        float* __restrict__ out) {
    __shared__ float bins[NBINS * ACC_THREADS];   // 32 KB, aliased by all roles
    __shared__ unsigned int s_round;
    int t = threadIdx.x;
    int bx = blockIdx.x;

    // ================= hist blocks: bid 0..15 =================
    if (bx < HISTB) {
        float* s_cc1 = bins;          // [128]
        float* s_cnt2 = bins + NBINS; // [128]
        s_cc1[t] = 0.f; s_cc1[t + 64] = 0.f;
        s_cnt2[t] = 0.f; s_cnt2[t + 64] = 0.f;
        __syncthreads();
        int h = bx;
        #pragma unroll
        for (int i = 0; i < 16; i++) {            // 16*64*16 = 16384 p1-groups
            int g = h * 1024 + i * 64 + t;
            int4 a = ((const int4*)p1)[g];
            atomicAdd(&s_cc1[p2[a.x]], 1.0f);
            atomicAdd(&s_cc1[p2[a.y]], 1.0f);
            atomicAdd(&s_cc1[p2[a.z]], 1.0f);
            atomicAdd(&s_cc1[p2[a.w]], 1.0f);
        }
        #pragma unroll
        for (int i = 0; i < 4; i++) {             // 16*64*4 = 4096 p2-groups
            int g = h * 256 + i * 64 + t;
            int4 b = ((const int4*)p2)[g];
            atomicAdd(&s_cnt2[b.x], 1.0f);
            atomicAdd(&s_cnt2[b.y], 1.0f);
            atomicAdd(&s_cnt2[b.z], 1.0f);
            atomicAdd(&s_cnt2[b.w], 1.0f);
        }
        __syncthreads();
        g_pcc1[t * HISTB + h]         = s_cc1[t];
        g_pcc1[(t + 64) * HISTB + h]  = s_cc1[t + 64];
        g_pcnt2[t * HISTB + h]        = s_cnt2[t];
        g_pcnt2[(t + 64) * HISTB + h] = s_cnt2[t + 64];
        __threadfence();
        __syncthreads();
        if (t == 0) atomicAdd(&c_aux, 1u);
        return;
    }

    // ================= fold blocks: bid 16..35, one per class =================
    if (bx < KBID) {
        float* u  = bins;        // [64]
        float* v  = bins + 64;   // [64]
        float* sA = bins + 128;  // [128]
        float* sB = bins + 256;
        float* sC = bins + 384;
        float* red = bins + 512; // [64]
        int cls = bx - HISTB;

        {   // u = W1@W0, v = W1@b0 (64 rows, 1/thread)
            float su = 0.f, sv = 0.f;
            #pragma unroll 8
            for (int c = 0; c < 32; c++) {
                float w = W1[t * 32 + c];
                su += w * W0[c]; sv += w * b0[c];
            }
            u[t] = su; v[t] = sv;
        }
        __syncthreads();
        #pragma unroll
        for (int hh = 0; hh < 2; hh++) {   // A/B/C rows t, t+64
            int row = t + 64 * hh;
            float sa = 0.f, sb = 0.f, sc = 0.f;
            #pragma unroll 8
            for (int c2 = 0; c2 < 64; c2++) {
                float w = W2[row * 64 + c2];
                sa += w * u[c2]; sb += w * v[c2]; sc += w * b1[c2];
            }
            sA[row] = sa; sB[row] = sb; sC[row] = sc;
        }
        __syncthreads();

        // G/GB/GC for m = t and t+64; D summed over both
        float G0 = 0.f, B0 = 0.f, C0 = 0.f;
        float G1 = 0.f, B1 = 0.f, C1 = 0.f;
        float D = 0.f;
        const float* fr = fcw + (size_t)cls * (128 * NBINS);
        #pragma unroll 8
        for (int c3 = 0; c3 < 128; c3++) {
            float w0 = fr[c3 * NBINS + t];
            float w1 = fr[c3 * NBINS + t + 64];
            float A = sA[c3], Bv = sB[c3], Cv = sC[c3], bb = b2[c3];
            G0 += w0 * A;  G1 += w1 * A;
            B0 += w0 * Bv; B1 += w1 * Bv;
            C0 += w0 * Cv; C1 += w1 * Cv;
            D += (w0 + w1) * bb;
        }
        g_G[cls * NBINS + t]       = G0;
        g_G[cls * NBINS + t + 64]  = G1;
        g_GB[cls * NBINS + t]      = B0;
        g_GB[cls * NBINS + t + 64] = B1;
        g_GC[cls * NBINS + t]      = C0;
        g_GC[cls * NBINS + t + 64] = C1;
        __syncthreads();   // bins reuse barrier
        red[t] = D;
        __syncthreads();
        #pragma unroll
        for (int s = 32; s > 0; s >>= 1) {
            if (t < s) red[t] += red[t + s];
            __syncthreads();
        }
        if (t == 0) g_GD[cls] = red[0];
        __threadfence();
        __syncthreads();
        if (t == 0) atomicAdd(&c_fold, 1u);
        return;
    }

    // ================= K block: bid 36 =================
    if (bx == KBID) {
        unsigned int R;
        if (t == 0) s_round = atomicAdd(&c_k, 1u);
        __syncthreads();
        R = s_round;
        if (t == 0) {
            spin_ge(&c_aux,  (R + 1) * HISTB);
            spin_ge(&c_fold, (R + 1) * FOLDB);
        }
        __syncthreads();
        __threadfence();

        // finalize cc1/cnt2 for m=t, t+64 (16 contiguous partials each)
        float cc0 = 0.f, cc1v = 0.f, cn0 = 0.f, cn1 = 0.f;
        {
            const float4* a0 = (const float4*)(g_pcc1 + t * HISTB);
            const float4* a1 = (const float4*)(g_pcc1 + (t + 64) * HISTB);
            const float4* b0v = (const float4*)(g_pcnt2 + t * HISTB);
            const float4* b1v = (const float4*)(g_pcnt2 + (t + 64) * HISTB);
            #pragma unroll
            for (int i = 0; i < HISTB / 4; i++) {
                float4 pa = a0[i], pb = a1[i], pc = b0v[i], pd = b1v[i];
                cc0  += pa.x + pa.y + pa.z + pa.w;
                cc1v += pb.x + pb.y + pb.z + pb.w;
                cn0  += pc.x + pc.y + pc.z + pc.w;
                cn1  += pd.x + pd.y + pd.z + pd.w;
            }
        }
        int lid = t & 31, wid = t >> 5;
        #pragma unroll
        for (int cls = 0; cls < NCLS; cls++) {
            float a = __ldcg(&g_GB[cls * NBINS + t]) * cc0
                    + __ldcg(&g_GB[cls * NBINS + t + 64]) * cc1v
                    + __ldcg(&g_GC[cls * NBINS + t]) * cn0
                    + __ldcg(&g_GC[cls * NBINS + t + 64]) * cn1;
            #pragma unroll
            for (int off = 16; off > 0; off >>= 1)
                a += __shfl_xor_sync(0xFFFFFFFFu, a, off);
            if (lid == 0) bins[cls * 2 + wid] = a;
        }
        __syncthreads();
        if (t < NCLS) bins[64 + t] = bins[t * 2] + bins[t * 2 + 1] + __ldcg(&g_GD[t]);
        __syncthreads();
        // seed out = fcb + K  (overwrites poison & previous launch)
        for (int i = t; i < BATCH * NCLS; i += ACC_THREADS)
            out[i] = fcb[i % NCLS] + bins[64 + i % NCLS];
        __threadfence();
        __syncthreads();
        if (t == 0) atomicAdd(&c_out, 1u);
        return;
    }

    // ================= accum blocks: bid 37..836 =================
    int a = bx - ACC0;

    // ---- phase 1: compose my slice of m8 ----
    for (int g = a * ACC_THREADS + t; g < NGROUPS; g += ACCB * ACC_THREADS) {
        int base = g * 4;
        unsigned int pack;
        if (base + 3 < IN_FEATURES) {
            int4 q = ((const int4*)p0)[g];
            int j0 = p1[q.x], j1 = p1[q.y], j2 = p1[q.z], j3 = p1[q.w];
            unsigned int m0 = p2[j0], m1 = p2[j1], m2 = p2[j2], m3 = p2[j3];
            pack = m0 | (m1 << 8) | (m2 << 16) | (m3 << 24);
        } else {
            pack = 0;
            for (int cc = 0; cc < 4; cc++)
                if (base + cc < IN_FEATURES)
                    pack |= ((unsigned int)p2[p1[p0[base + cc]]]) << (8 * cc);
        }
        g_m8[g] = pack;
    }
    __threadfence();
    __syncthreads();
    unsigned int round;
    if (t == 0) {
        unsigned int tk = atomicAdd(&c_compose, 1u);
        s_round = tk / ACCB;
        spin_ge(&c_compose, (s_round + 1) * ACCB);   // grid barrier over accum blocks
    }
    __syncthreads();
    round = s_round;
    __threadfence();

    // ---- phase 2: binning ----
    int c = a % ACC_CHUNKS;
    int r = a / ACC_CHUNKS;
    #pragma unroll
    for (int b = 0; b < NBINS; b++) bins[b * ACC_THREADS + t] = 0.f;
    __syncthreads();

    const float* xr = x + (size_t)r * IN_FEATURES;
    int p = (4 - (r & 3)) & 3;                 // alignment phase (IN%4==1)
    int Kv = (IN_FEATURES - p) >> 2;
    int ck = (Kv + ACC_CHUNKS - 1) / ACC_CHUNKS;
    int k0 = c * ck;
    int k1 = min(k0 + ck, Kv);

    const unsigned int* mu = g_m8;
    const float4* xv = (const float4*)(xr + p);
    int sh = 8 * p;

    for (int k = k0 + t; k < k1; k += ACC_THREADS) {
        unsigned int u0 = mu[k], u1 = mu[k + 1];
        unsigned int b = __funnelshift_r(u0, u1, sh);
        float4 X = xv[k];
        bins[(int)(b & 255u)         * ACC_THREADS + t] += X.x;
        bins[(int)((b >> 8) & 255u)  * ACC_THREADS + t] += X.y;
        bins[(int)((b >> 16) & 255u) * ACC_THREADS + t] += X.z;
        bins[(int)(b >> 24)          * ACC_THREADS + t] += X.w;
    }

    const unsigned char* m8b = (const unsigned char*)g_m8;
    if (c == 0 && t < p) {
        bins[(int)m8b[t] * ACC_THREADS + t] += xr[t];
    }
    int tail0 = p + 4 * Kv;
    int ntail = IN_FEATURES - tail0;
    if (c == ACC_CHUNKS - 1 && t < ntail) {
        bins[(int)m8b[tail0 + t] * ACC_THREADS + t] += xr[tail0 + t];
    }
    __syncthreads();

    // reduce 64 private columns: thread t owns bins t and t+64
    float s0 = 0.f, s1 = 0.f;
    #pragma unroll 8
    for (int l = 0; l < ACC_THREADS; l++) {
        int lc = (l + t) & (ACC_THREADS - 1);
        s0 += bins[t * ACC_THREADS + lc];
        s1 += bins[(t + 64) * ACC_THREADS + lc];
    }

    // ---- phase 3: wait for out-seed (implies fold done), then dot with G ----
    if (t == 0) spin_ge(&c_out, round + 1);
    __syncthreads();
    __threadfence();

    int lid = t & 31;
    #pragma unroll
    for (int cls = 0; cls < NCLS; cls++) {
        float av = __ldcg(&g_G[cls * NBINS + t]) * s0
                 + __ldcg(&g_G[cls * NBINS + t + 64]) * s1;
        #pragma unroll
        for (int off = 16; off > 0; off >>= 1)
            av += __shfl_xor_sync(0xFFFFFFFFu, av, off);
        if (lid == 0) atomicAdd(&out[r * NCLS + cls], av);
    }
}

// ---------------- launch: ONE kernel, one graph node ----------------
extern "C" void kernel_launch(void* const* d_in, const int* in_sizes, int n_in,
                              void* d_out, int out_size) {
    const float* x   = (const float*)d_in[0];
    const float* W0  = (const float*)d_in[1];
    const float* b0  = (const float*)d_in[2];
    const float* W1  = (const float*)d_in[3];
    const float* b1  = (const float*)d_in[4];
    const float* W2  = (const float*)d_in[5];
    const float* b2  = (const float*)d_in[6];
    const float* fcw = (const float*)d_in[7];
    const float* fcb = (const float*)d_in[8];
    const int*   p0  = (const int*)d_in[9];
    const int*   p1  = (const int*)d_in[10];
    const int*   p2  = (const int*)d_in[11];
    float* out = (float*)d_out;

    mega_kernel<<<TOTALB, ACC_THREADS>>>(x, p0, p1, p2, W0, b0, W1, b1, W2, b2,
                                         fcw, fcb, out);
}

// round 14
// speedup vs baseline: 1.8913x; 1.8913x over previous
#include <cuda_runtime.h>

#define IN_FEATURES 212445
#define N1 65536
#define N2 16384
#define NBINS 128
#define NCLS 20
#define BATCH 32

#define ACC_THREADS 64
#define ACC_CHUNKS 27
#define NGROUPS ((IN_FEATURES + 3) / 4)   // 53112 groups of 4 features

#define QB 128
#define QT 512

#define CB ((NGROUPS + 255) / 256)        // 208 compose blocks
#define FCHUNKS 8
#define FOLD_BLOCKS (FCHUNKS * NCLS)      // 160

// ---------------- device scratch (no allocation allowed) ----------------
// contiguous zero block: [Gt (128*20, layout [m][cls])] [cc1 (128)] [cnt2 (128)]
__device__ float g_zero[NBINS * NCLS + 2 * NBINS];
#define G_GT   (g_zero)
#define G_CC1  (g_zero + NBINS * NCLS)
#define G_CNT2 (g_zero + NBINS * NCLS + NBINS)

__device__ unsigned char g_q[N1 + 4];            // q[j] = p2[p1[j]]
__device__ unsigned int g_m8[NGROUPS];           // composed map, 4 bins packed/uint
__device__ float g_A[128], g_B[128], g_C[128];   // folded weight vectors

// ---------------- K1: q table + histograms (global atomics) + A/B/C + seed out ----------------
__global__ void __launch_bounds__(QT) q_kernel(const int* __restrict__ p1,
                                               const int* __restrict__ p2,
                                               const float* __restrict__ W0,
                                               const float* __restrict__ b0,
                                               const float* __restrict__ W1,
                                               const float* __restrict__ b1,
                                               const float* __restrict__ W2,
                                               const float* __restrict__ fcb,
                                               float* __restrict__ out) {
    int t = threadIdx.x;
    if (blockIdx.x == QB) {
        // fold weights: u = W1@W0, v = W1@b0; A = W2@u, B = W2@v, C = W2@b1
        __shared__ float u[64], v[64];
        if (t < 64) {
            float su = 0.f, sv = 0.f;
            #pragma unroll 8
            for (int c = 0; c < 32; c++) {
                float w = W1[t * 32 + c];
                su += w * W0[c];
                sv += w * b0[c];
            }
            u[t] = su; v[t] = sv;
        }
        __syncthreads();
        if (t < 128) {
            float sa = 0.f, sb = 0.f, sc = 0.f;
            #pragma unroll 8
            for (int c2 = 0; c2 < 64; c2++) {
                float w = W2[t * 64 + c2];
                sa += w * u[c2]; sb += w * v[c2]; sc += w * b1[c2];
            }
            g_A[t] = sa; g_B[t] = sb; g_C[t] = sc;
        }
        // seed out with fcb (atomics accumulate onto this)
        for (int i = t; i < BATCH * NCLS; i += QT) out[i] = fcb[i % NCLS];
        return;
    }

    __shared__ float s_cc1[NBINS], s_cnt2[NBINS];
    int gid = blockIdx.x * QT + t;
    if (t < NBINS) { s_cc1[t] = 0.f; s_cnt2[t] = 0.f; }
    __syncthreads();

    // q[j] = p2[p1[j]]; cc1 = histogram of q; cnt2 = histogram of p2
    int m = p2[p1[gid]];
    g_q[gid] = (unsigned char)m;
    atomicAdd(&s_cc1[m], 1.0f);
    if (gid < N2) atomicAdd(&s_cnt2[p2[gid]], 1.0f);

    __syncthreads();
    if (t < NBINS) {
        if (s_cc1[t] != 0.f)  atomicAdd(&G_CC1[t], s_cc1[t]);
        if (s_cnt2[t] != 0.f) atomicAdd(&G_CNT2[t], s_cnt2[t]);
    }
}

// ---------------- K2: compose (blocks [0,CB)) + fcw fold (blocks [CB,CB+160)) ----------------
__global__ void __launch_bounds__(256) compose_kernel(const int* __restrict__ p0,
                                                      const float* __restrict__ b2,
                                                      const float* __restrict__ fcw,
                                                      float* __restrict__ out) {
    int t = threadIdx.x;
    int bx = blockIdx.x;

    if (bx >= CB) {
        // ---- fold block: (chunk, cls); 256 threads = 128 m x 2 c3-halves of 8 ----
        __shared__ float red[256];
        int fb = bx - CB;
        int chunk = fb & (FCHUNKS - 1);
        int cls = fb >> 3;
        int m = t & 127;
        int half = t >> 7;
        int c3_0 = chunk * 16 + half * 8;

        float pG = 0.f, pB = 0.f, pC = 0.f, pD = 0.f;
        const float* fr = fcw + (size_t)cls * (128 * NBINS) + (size_t)c3_0 * NBINS + m;
        #pragma unroll
        for (int i = 0; i < 8; i++) {
            float w = fr[i * NBINS];
            int c3 = c3_0 + i;
            pG += w * g_A[c3];
            pB += w * g_B[c3];
            pC += w * g_C[c3];
            pD += w * b2[c3];
        }
        // transposed layout: G_GT[m][cls]
        atomicAdd(&G_GT[m * NCLS + cls], pG);

        red[t] = pB * G_CC1[m] + pC * G_CNT2[m] + pD;
        __syncthreads();
        #pragma unroll
        for (int s = 128; s > 0; s >>= 1) {
            if (t < s) red[t] += red[t + s];
            __syncthreads();
        }
        if (t < BATCH) atomicAdd(&out[t * NCLS + cls], red[0]);
        return;
    }

    // ---- compose block: m8[i] = q[p0[i]] ----
    const unsigned char* q8 = g_q;
    int gid = bx * 256 + t;
    if (gid >= NGROUPS) return;
    int base = gid * 4;
    unsigned int pack;
    if (base + 3 < IN_FEATURES) {
        int4 a = ((const int4*)p0)[gid];
        unsigned int m0 = q8[a.x], m1 = q8[a.y], m2 = q8[a.z], m3 = q8[a.w];
        pack = m0 | (m1 << 8) | (m2 << 16) | (m3 << 24);
    } else {
        pack = 0;
        for (int c = 0; c < 4; c++)
            if (base + c < IN_FEATURES)
                pack |= ((unsigned int)q8[p0[base + c]]) << (8 * c);
    }
    g_m8[gid] = pack;
}

// ---------------- K3: accum + per-block logits contribution ----------------
__global__ void __launch_bounds__(ACC_THREADS) accum_kernel(const float* __restrict__ x,
                                                            float* __restrict__ out) {
    __shared__ float bins[NBINS * ACC_THREADS];  // 32 KB
    __shared__ float sm2[NBINS];                 // staged bin sums
    int t = threadIdx.x;
    int c = blockIdx.x % ACC_CHUNKS;
    int r = blockIdx.x / ACC_CHUNKS;
    #pragma unroll
    for (int b = 0; b < NBINS; b++) bins[b * ACC_THREADS + t] = 0.f;

    const float* xr = x + (size_t)r * IN_FEATURES;
    int p = (4 - (r & 3)) & 3;                 // alignment phase (IN%4==1)
    int Kv = (IN_FEATURES - p) >> 2;
    int ck = (Kv + ACC_CHUNKS - 1) / ACC_CHUNKS;
    int k0 = c * ck;
    int k1 = min(k0 + ck, Kv);

    const unsigned int* mu = g_m8;
    const float4* xv = (const float4*)(xr + p);
    int sh = 8 * p;

    for (int k = k0 + t; k < k1; k += ACC_THREADS) {
        unsigned int u0 = mu[k], u1 = mu[k + 1];
        unsigned int b = __funnelshift_r(u0, u1, sh);
        float4 X = xv[k];
        bins[(int)(b & 255u)         * ACC_THREADS + t] += X.x;
        bins[(int)((b >> 8) & 255u)  * ACC_THREADS + t] += X.y;
        bins[(int)((b >> 16) & 255u) * ACC_THREADS + t] += X.z;
        bins[(int)(b >> 24)          * ACC_THREADS + t] += X.w;
    }

    const unsigned char* m8b = (const unsigned char*)g_m8;
    if (c == 0 && t < p) {
        bins[(int)m8b[t] * ACC_THREADS + t] += xr[t];
    }
    int tail0 = p + 4 * Kv;
    int ntail = IN_FEATURES - tail0;
    if (c == ACC_CHUNKS - 1 && t < ntail) {
        bins[(int)m8b[tail0 + t] * ACC_THREADS + t] += xr[tail0 + t];
    }
    __syncthreads();

    // reduce 64 private columns: thread t owns bins t and t+64
    float s0 = 0.f, s1 = 0.f;
    #pragma unroll 8
    for (int l = 0; l < ACC_THREADS; l++) {
        int lc = (l + t) & (ACC_THREADS - 1);
        s0 += bins[t * ACC_THREADS + lc];
        s1 += bins[(t + 64) * ACC_THREADS + lc];
    }
    sm2[t] = s0;
    sm2[t + 64] = s1;
    __syncthreads();

    // transposed dot: threads 0..39 -> (cls = t%20, half = t/20), 64 FMAs each,
    // coalesced loads from G_GT[m][cls]; one atomicAdd per thread.
    if (t < 2 * NCLS) {
        int cls = t % NCLS;
        int half = t / NCLS;
        int mbase = half * 64;
        float a0 = 0.f, a1 = 0.f;
        const float* gt = G_GT + (size_t)mbase * NCLS + cls;
        #pragma unroll 8
        for (int j = 0; j < 64; j += 2) {
            a0 += gt[j * NCLS]       * sm2[mbase + j];
            a1 += gt[(j + 1) * NCLS] * sm2[mbase + j + 1];
        }
        atomicAdd(&out[r * NCLS + cls], a0 + a1);
    }
}

// ---------------- launch ----------------
extern "C" void kernel_launch(void* const* d_in, const int* in_sizes, int n_in,
                              void* d_out, int out_size) {
    const float* x   = (const float*)d_in[0];
    const float* W0  = (const float*)d_in[1];
    const float* b0  = (const float*)d_in[2];
    const float* W1  = (const float*)d_in[3];
    const float* b1  = (const float*)d_in[4];
    const float* W2  = (const float*)d_in[5];
    const float* b2  = (const float*)d_in[6];
    const float* fcw = (const float*)d_in[7];
    const float* fcb = (const float*)d_in[8];
    const int*   p0  = (const int*)d_in[9];
    const int*   p1  = (const int*)d_in[10];
    const int*   p2  = (const int*)d_in[11];
    float* out = (float*)d_out;

    void* zp = nullptr;
    cudaGetSymbolAddress(&zp, g_zero);
    cudaMemsetAsync(zp, 0, sizeof(float) * (NBINS * NCLS + 2 * NBINS));

    q_kernel<<<QB + 1, QT>>>(p1, p2, W0, b0, W1, b1, W2, fcb, out);
    compose_kernel<<<CB + FOLD_BLOCKS, 256>>>(p0, b2, fcw, out);
    accum_kernel<<<ACC_CHUNKS * BATCH, ACC_THREADS>>>(x, out);
}